// round 1
// baseline (speedup 1.0000x reference)
#include <cuda_runtime.h>
#include <cuda_bf16.h>
#include <math.h>

#define NN 100000
#define EE 300000
#define CH 256
#define LL 8
#define NCLS 40
#define SCAN_BS 1024
#define SCAN_NB 98   // ceil(100000/1024)

// ---------------- device scratch (no allocations allowed) ----------------
__device__ float g_h0[(size_t)NN * CH];
__device__ float g_h [(size_t)NN * CH];
__device__ float g_x [(size_t)NN * CH];
__device__ float g_W [(size_t)LL * CH * CH];
__device__ int   g_deg[NN];
__device__ int   g_rs [NN];
__device__ int   g_cur[NN];
__device__ int   g_incl[NN];
__device__ int   g_bsum[SCAN_NB];
__device__ int   g_boff[SCAN_NB];
__device__ int   g_csrc[EE];

// ---------------- weight prep: M_l = beta_l * W_l + (1-beta_l) * I --------
__global__ void k_prep_w(const float* __restrict__ gcn_w) {
    int idx = blockIdx.x * blockDim.x + threadIdx.x;
    if (idx >= LL * CH * CH) return;
    int l  = idx >> 16;          // /65536
    int rc = idx & 65535;
    int r = rc >> 8, c = rc & 255;
    float beta = logf(0.5f / (float)(l + 1) + 1.0f);
    float w = gcn_w[idx];
    g_W[idx] = beta * w + ((r == c) ? (1.0f - beta) : 0.0f);
}

// ---------------- CSR build ----------------
__global__ void k_zero_deg() {
    int i = blockIdx.x * blockDim.x + threadIdx.x;
    if (i < NN) g_deg[i] = 0;
}

__global__ void k_hist(const int* __restrict__ dst) {
    int e = blockIdx.x * blockDim.x + threadIdx.x;
    if (e < EE) atomicAdd(&g_deg[dst[e]], 1);
}

__global__ void k_scan1() {
    __shared__ int sm[SCAN_BS];
    int tid = threadIdx.x;
    int i = blockIdx.x * SCAN_BS + tid;
    int v = (i < NN) ? g_deg[i] : 0;
    sm[tid] = v;
    __syncthreads();
    for (int off = 1; off < SCAN_BS; off <<= 1) {
        int t = (tid >= off) ? sm[tid - off] : 0;
        __syncthreads();
        sm[tid] += t;
        __syncthreads();
    }
    if (i < NN) g_incl[i] = sm[tid];
    if (tid == SCAN_BS - 1) g_bsum[blockIdx.x] = sm[tid];
}

__global__ void k_scan2() {
    if (threadIdx.x == 0) {
        int s = 0;
        for (int b = 0; b < SCAN_NB; b++) { g_boff[b] = s; s += g_bsum[b]; }
    }
}

__global__ void k_scan3() {
    int i = blockIdx.x * blockDim.x + threadIdx.x;
    if (i >= NN) return;
    int rs = g_boff[i >> 10] + g_incl[i] - g_deg[i];
    g_rs[i] = rs;
    g_cur[i] = rs;
}

__global__ void k_scatter(const int* __restrict__ src, const int* __restrict__ dst) {
    int e = blockIdx.x * blockDim.x + threadIdx.x;
    if (e >= EE) return;
    int p = atomicAdd(&g_cur[dst[e]], 1);
    g_csrc[p] = src[e];
}

// ---------------- aggregation: x = 0.9 * sum_{src->node} h[src] + 0.1 * h0 ----
__global__ void k_agg() {
    int node = blockIdx.x * blockDim.y + threadIdx.y;
    if (node >= NN) return;
    int lane = threadIdx.x;
    int s = g_rs[node], d = g_deg[node];
    float4 a0 = make_float4(0.f, 0.f, 0.f, 0.f);
    float4 a1 = make_float4(0.f, 0.f, 0.f, 0.f);
    for (int e = 0; e < d; e++) {
        int sn = g_csrc[s + e];
        const float4* hp = (const float4*)(g_h + (size_t)sn * CH);
        float4 v = hp[lane];
        a0.x += v.x; a0.y += v.y; a0.z += v.z; a0.w += v.w;
        v = hp[lane + 32];
        a1.x += v.x; a1.y += v.y; a1.z += v.z; a1.w += v.w;
    }
    const float4* h0p = (const float4*)(g_h0 + (size_t)node * CH);
    float4 z0 = h0p[lane], z1 = h0p[lane + 32];
    float4 o0, o1;
    o0.x = 0.9f * a0.x + 0.1f * z0.x;  o0.y = 0.9f * a0.y + 0.1f * z0.y;
    o0.z = 0.9f * a0.z + 0.1f * z0.z;  o0.w = 0.9f * a0.w + 0.1f * z0.w;
    o1.x = 0.9f * a1.x + 0.1f * z1.x;  o1.y = 0.9f * a1.y + 0.1f * z1.y;
    o1.z = 0.9f * a1.z + 0.1f * z1.z;  o1.w = 0.9f * a1.w + 0.1f * z1.w;
    float4* xp = (float4*)(g_x + (size_t)node * CH);
    xp[lane] = o0;
    xp[lane + 32] = o1;
}

// ---------------- 128x128 tiled fp32 GEMM + optional bias + ReLU ----------
// C[row, ccol0 + n0 + j] = relu( sum_k A[row,k] * B[k, n0+j] + bias[n0+j] )
// A is [M, 256] row-major (K fixed = 256). B is [256, ldb].
__global__ void __launch_bounds__(256, 2)
k_gemm(const float* __restrict__ A, const float* __restrict__ B, int ldb,
       const float* __restrict__ bias, float* __restrict__ C,
       float* __restrict__ C2, int ccol0, int M) {
    __shared__ float As[2][8][128];
    __shared__ float Bs[2][8][128];
    const int tid = threadIdx.x;
    const int m0 = blockIdx.x * 128;
    const int n0 = blockIdx.y * 128;

    const int rowA = tid >> 1;          // 0..127
    const int kA   = (tid & 1) * 4;     // 0 or 4
    const int kB   = tid >> 5;          // 0..7
    const int nB   = (tid & 31) * 4;    // 0..124

    const int tx = tid & 15, ty = tid >> 4;

    float acc[8][8];
    #pragma unroll
    for (int i = 0; i < 8; i++)
        #pragma unroll
        for (int j = 0; j < 8; j++) acc[i][j] = 0.f;

    // prologue: load tile 0
    {
        float4 av = make_float4(0.f, 0.f, 0.f, 0.f);
        if (m0 + rowA < M) av = *(const float4*)(A + (size_t)(m0 + rowA) * CH + kA);
        As[0][kA + 0][rowA] = av.x; As[0][kA + 1][rowA] = av.y;
        As[0][kA + 2][rowA] = av.z; As[0][kA + 3][rowA] = av.w;
        float4 bv = *(const float4*)(B + (size_t)kB * ldb + n0 + nB);
        *(float4*)&Bs[0][kB][nB] = bv;
    }
    __syncthreads();

    const int NIT = CH / 8;
    for (int it = 0; it < NIT; ++it) {
        const int cur = it & 1;
        float4 av, bv;
        const bool has_next = (it + 1 < NIT);
        if (has_next) {
            const int kt = (it + 1) * 8;
            av = make_float4(0.f, 0.f, 0.f, 0.f);
            if (m0 + rowA < M) av = *(const float4*)(A + (size_t)(m0 + rowA) * CH + kt + kA);
            bv = *(const float4*)(B + (size_t)(kt + kB) * ldb + n0 + nB);
        }
        #pragma unroll
        for (int k = 0; k < 8; ++k) {
            float4 a0 = *(const float4*)&As[cur][k][ty * 8];
            float4 a1 = *(const float4*)&As[cur][k][ty * 8 + 4];
            float4 b0 = *(const float4*)&Bs[cur][k][tx * 8];
            float4 b1 = *(const float4*)&Bs[cur][k][tx * 8 + 4];
            float fa[8] = {a0.x, a0.y, a0.z, a0.w, a1.x, a1.y, a1.z, a1.w};
            float fb[8] = {b0.x, b0.y, b0.z, b0.w, b1.x, b1.y, b1.z, b1.w};
            #pragma unroll
            for (int i = 0; i < 8; i++)
                #pragma unroll
                for (int j = 0; j < 8; j++)
                    acc[i][j] = fmaf(fa[i], fb[j], acc[i][j]);
        }
        if (has_next) {
            const int nb = cur ^ 1;
            As[nb][kA + 0][rowA] = av.x; As[nb][kA + 1][rowA] = av.y;
            As[nb][kA + 2][rowA] = av.z; As[nb][kA + 3][rowA] = av.w;
            *(float4*)&Bs[nb][kB][nB] = bv;
        }
        __syncthreads();
    }

    // epilogue: bias + relu + store (float4 x2 per row)
    #pragma unroll
    for (int i = 0; i < 8; i++) {
        const int row = m0 + ty * 8 + i;
        if (row >= M) continue;
        #pragma unroll
        for (int j = 0; j < 8; j += 4) {
            const int col = n0 + tx * 8 + j;
            float4 v;
            v.x = acc[i][j + 0]; v.y = acc[i][j + 1];
            v.z = acc[i][j + 2]; v.w = acc[i][j + 3];
            if (bias) {
                v.x += bias[col + 0]; v.y += bias[col + 1];
                v.z += bias[col + 2]; v.w += bias[col + 3];
            }
            v.x = fmaxf(v.x, 0.f); v.y = fmaxf(v.y, 0.f);
            v.z = fmaxf(v.z, 0.f); v.w = fmaxf(v.w, 0.f);
            *(float4*)(C + (size_t)row * CH + ccol0 + col) = v;
            if (C2) *(float4*)(C2 + (size_t)row * CH + ccol0 + col) = v;
        }
    }
}

// ---------------- final projection: out = h @ out_w + out_b  [N,40] ------
__global__ void __launch_bounds__(256)
k_out(const float* __restrict__ H, const float* __restrict__ Wo,
      const float* __restrict__ bo, float* __restrict__ O) {
    __shared__ float As[256][33];
    __shared__ float Ws[32][40];
    const int tid = threadIdx.x;
    const int m0 = blockIdx.x * 256;
    const int rg = tid >> 1;       // 0..127 -> rows rg*2, rg*2+1
    const int cg = tid & 1;        // cols cg*20 .. cg*20+19

    float acc[2][20];
    #pragma unroll
    for (int r = 0; r < 2; r++)
        #pragma unroll
        for (int j = 0; j < 20; j++) acc[r][j] = 0.f;

    for (int kt = 0; kt < CH; kt += 32) {
        #pragma unroll
        for (int i = 0; i < 8; i++) {
            int idx = tid + i * 256;           // 0..2047
            int r = idx >> 3, kq = (idx & 7) * 4;
            float4 v = make_float4(0.f, 0.f, 0.f, 0.f);
            int row = m0 + r;
            if (row < NN) v = *(const float4*)(H + (size_t)row * CH + kt + kq);
            As[r][kq + 0] = v.x; As[r][kq + 1] = v.y;
            As[r][kq + 2] = v.z; As[r][kq + 3] = v.w;
        }
        for (int i = tid; i < 32 * NCLS; i += 256)
            Ws[i / NCLS][i % NCLS] = Wo[(size_t)(kt + i / NCLS) * NCLS + (i % NCLS)];
        __syncthreads();
        #pragma unroll
        for (int k = 0; k < 32; k++) {
            float a0 = As[rg * 2 + 0][k];
            float a1 = As[rg * 2 + 1][k];
            #pragma unroll
            for (int j = 0; j < 20; j++) {
                float w = Ws[k][cg * 20 + j];
                acc[0][j] = fmaf(a0, w, acc[0][j]);
                acc[1][j] = fmaf(a1, w, acc[1][j]);
            }
        }
        __syncthreads();
    }
    #pragma unroll
    for (int rr = 0; rr < 2; rr++) {
        int row = m0 + rg * 2 + rr;
        if (row >= NN) continue;
        #pragma unroll
        for (int j = 0; j < 20; j++) {
            int col = cg * 20 + j;
            O[(size_t)row * NCLS + col] = acc[rr][j] + bo[col];
        }
    }
}

// ---------------- launch ----------------
extern "C" void kernel_launch(void* const* d_in, const int* in_sizes, int n_in,
                              void* d_out, int out_size) {
    const float* x0    = (const float*)d_in[0];
    const float* x1    = (const float*)d_in[1];
    const int*   ei    = (const int*)d_in[2];
    const float* lin_w = (const float*)d_in[3];
    const float* lin_b = (const float*)d_in[4];
    const float* gcn_w = (const float*)d_in[5];
    const float* out_w = (const float*)d_in[6];
    const float* out_b = (const float*)d_in[7];
    float* out = (float*)d_out;

    const int* e_src = ei;
    const int* e_dst = ei + EE;

    float *p_h0, *p_h, *p_x, *p_W;
    cudaGetSymbolAddress((void**)&p_h0, g_h0);
    cudaGetSymbolAddress((void**)&p_h,  g_h);
    cudaGetSymbolAddress((void**)&p_x,  g_x);
    cudaGetSymbolAddress((void**)&p_W,  g_W);

    // effective weights
    k_prep_w<<<(LL * CH * CH + 255) / 256, 256>>>(gcn_w);

    // CSR build
    k_zero_deg<<<(NN + 255) / 256, 256>>>();
    k_hist<<<(EE + 255) / 256, 256>>>(e_dst);
    k_scan1<<<SCAN_NB, SCAN_BS>>>();
    k_scan2<<<1, 32>>>();
    k_scan3<<<(NN + 255) / 256, 256>>>();
    k_scatter<<<(EE + 255) / 256, 256>>>(e_src, e_dst);

    const int mtiles = (NN + 127) / 128;

    // h0 = concat(relu(x0@W0+b0), relu(x1@W1+b1)); h = h0
    k_gemm<<<dim3(mtiles, 1), 256>>>(x0, lin_w,            128, lin_b,       p_h0, p_h, 0,   NN);
    k_gemm<<<dim3(mtiles, 1), 256>>>(x1, lin_w + 256 * 128, 128, lin_b + 128, p_h0, p_h, 128, NN);

    // 8 GCNII layers
    for (int l = 0; l < LL; l++) {
        k_agg<<<(NN + 7) / 8, dim3(32, 8)>>>();
        k_gemm<<<dim3(mtiles, 2), 256>>>(p_x, p_W + (size_t)l * CH * CH, CH,
                                         nullptr, p_h, nullptr, 0, NN);
    }

    // output projection
    k_out<<<(NN + 255) / 256, 256>>>(p_h, out_w, out_b, out);
}

// round 3
// speedup vs baseline: 1.9249x; 1.9249x over previous
#include <cuda_runtime.h>
#include <cuda_bf16.h>
#include <math.h>
#include <stdint.h>

#define NN 100000
#define EE 300000
#define CH 256
#define LL 8
#define NCLS 40
#define SCAN_BS 1024
#define SCAN_NB 98   // ceil(100000/1024)

// ---------------- helpers ----------------
__device__ __forceinline__ uint32_t smem_u32(const void* p) {
    uint32_t a;
    asm("{ .reg .u64 t; cvta.to.shared.u64 t, %1; cvt.u32.u64 %0, t; }" : "=r"(a) : "l"(p));
    return a;
}

__device__ __forceinline__ void ldsm_x4(uint32_t* r, uint32_t addr) {
    asm volatile("ldmatrix.sync.aligned.m8n8.x4.shared.b16 {%0,%1,%2,%3}, [%4];"
                 : "=r"(r[0]), "=r"(r[1]), "=r"(r[2]), "=r"(r[3]) : "r"(addr));
}
__device__ __forceinline__ void ldsm_x2(uint32_t* r, uint32_t addr) {
    asm volatile("ldmatrix.sync.aligned.m8n8.x2.shared.b16 {%0,%1}, [%2];"
                 : "=r"(r[0]), "=r"(r[1]) : "r"(addr));
}
__device__ __forceinline__ void mma16816(float* d, const uint32_t* a, const uint32_t* b) {
    asm volatile(
        "mma.sync.aligned.m16n8k16.row.col.f32.bf16.bf16.f32 "
        "{%0,%1,%2,%3}, {%4,%5,%6,%7}, {%8,%9}, {%0,%1,%2,%3};"
        : "+f"(d[0]), "+f"(d[1]), "+f"(d[2]), "+f"(d[3])
        : "r"(a[0]), "r"(a[1]), "r"(a[2]), "r"(a[3]), "r"(b[0]), "r"(b[1]));
}

// ---------------- device scratch (no allocations allowed) ----------------
__device__ float g_h0[(size_t)NN * CH];
__device__ float g_h [(size_t)NN * CH];
__device__ float g_x [(size_t)NN * CH];
__device__ __nv_bfloat16 g_Bh [(size_t)LL * 256 * 256];   // gcn eff weights [l][n][k], hi
__device__ __nv_bfloat16 g_Bl [(size_t)LL * 256 * 256];   // lo
__device__ __nv_bfloat16 g_BLh[(size_t)2 * 128 * 256];    // lin weights [v][n][k], hi
__device__ __nv_bfloat16 g_BLl[(size_t)2 * 128 * 256];    // lo
__device__ int   g_deg[NN];
__device__ int   g_rs [NN];
__device__ int   g_cur[NN];
__device__ int   g_incl[NN];
__device__ int   g_bsum[SCAN_NB];
__device__ int   g_boff[SCAN_NB];
__device__ int   g_csrc[EE];

// ---------------- weight prep ----------------
// gcn: Beff[n][k] = beta_l * W_l[k][n] + (n==k)*(1-beta_l), hi/lo split.
__global__ void k_prep_gcn(const float* __restrict__ gcn_w) {
    int idx = blockIdx.x * blockDim.x + threadIdx.x;
    if (idx >= LL * 256 * 256) return;
    int l = idx >> 16;
    int n = (idx >> 8) & 255;
    int k = idx & 255;
    float beta = logf(0.5f / (float)(l + 1) + 1.0f);
    float w = gcn_w[l * 65536 + k * 256 + n];
    float eff = beta * w + ((n == k) ? (1.0f - beta) : 0.0f);
    __nv_bfloat16 hi = __float2bfloat16(eff);
    __nv_bfloat16 lo = __float2bfloat16(eff - __bfloat162float(hi));
    g_Bh[idx] = hi;
    g_Bl[idx] = lo;
}

// lin: B[v][n][k] = lin_w[v][k][n]
__global__ void k_prep_lin(const float* __restrict__ lin_w) {
    int idx = blockIdx.x * blockDim.x + threadIdx.x;
    if (idx >= 2 * 128 * 256) return;
    int v = idx >> 15;
    int n = (idx >> 8) & 127;
    int k = idx & 255;
    float w = lin_w[v * 32768 + k * 128 + n];
    __nv_bfloat16 hi = __float2bfloat16(w);
    __nv_bfloat16 lo = __float2bfloat16(w - __bfloat162float(hi));
    g_BLh[idx] = hi;
    g_BLl[idx] = lo;
}

// ---------------- CSR build ----------------
__global__ void k_zero_deg() {
    int i = blockIdx.x * blockDim.x + threadIdx.x;
    if (i < NN) g_deg[i] = 0;
}
__global__ void k_hist(const int* __restrict__ dst) {
    int e = blockIdx.x * blockDim.x + threadIdx.x;
    if (e < EE) atomicAdd(&g_deg[dst[e]], 1);
}
__global__ void k_scan1() {
    __shared__ int sm[SCAN_BS];
    int tid = threadIdx.x;
    int i = blockIdx.x * SCAN_BS + tid;
    int v = (i < NN) ? g_deg[i] : 0;
    sm[tid] = v;
    __syncthreads();
    for (int off = 1; off < SCAN_BS; off <<= 1) {
        int t = (tid >= off) ? sm[tid - off] : 0;
        __syncthreads();
        sm[tid] += t;
        __syncthreads();
    }
    if (i < NN) g_incl[i] = sm[tid];
    if (tid == SCAN_BS - 1) g_bsum[blockIdx.x] = sm[tid];
}
__global__ void k_scan2() {
    if (threadIdx.x == 0) {
        int s = 0;
        for (int b = 0; b < SCAN_NB; b++) { g_boff[b] = s; s += g_bsum[b]; }
    }
}
__global__ void k_scan3() {
    int i = blockIdx.x * blockDim.x + threadIdx.x;
    if (i >= NN) return;
    int rs = g_boff[i >> 10] + g_incl[i] - g_deg[i];
    g_rs[i] = rs;
    g_cur[i] = rs;
}
__global__ void k_scatter(const int* __restrict__ src, const int* __restrict__ dst) {
    int e = blockIdx.x * blockDim.x + threadIdx.x;
    if (e >= EE) return;
    int p = atomicAdd(&g_cur[dst[e]], 1);
    g_csrc[p] = src[e];
}

// ---------------- aggregation: x = 0.9 * sum_{src->node} h[src] + 0.1 * h0 ----
__global__ void k_agg() {
    int node = blockIdx.x * blockDim.y + threadIdx.y;
    if (node >= NN) return;
    int lane = threadIdx.x;
    int s = g_rs[node], d = g_deg[node];
    float4 a0 = make_float4(0.f, 0.f, 0.f, 0.f);
    float4 a1 = make_float4(0.f, 0.f, 0.f, 0.f);
    int e = 0;
    for (; e + 2 <= d; e += 2) {
        int s1 = g_csrc[s + e], s2 = g_csrc[s + e + 1];
        const float4* h1 = (const float4*)(g_h + (size_t)s1 * CH);
        const float4* h2 = (const float4*)(g_h + (size_t)s2 * CH);
        float4 v0 = h1[lane], v1 = h1[lane + 32];
        float4 w0 = h2[lane], w1 = h2[lane + 32];
        a0.x += v0.x + w0.x; a0.y += v0.y + w0.y; a0.z += v0.z + w0.z; a0.w += v0.w + w0.w;
        a1.x += v1.x + w1.x; a1.y += v1.y + w1.y; a1.z += v1.z + w1.z; a1.w += v1.w + w1.w;
    }
    if (e < d) {
        int s1 = g_csrc[s + e];
        const float4* h1 = (const float4*)(g_h + (size_t)s1 * CH);
        float4 v0 = h1[lane], v1 = h1[lane + 32];
        a0.x += v0.x; a0.y += v0.y; a0.z += v0.z; a0.w += v0.w;
        a1.x += v1.x; a1.y += v1.y; a1.z += v1.z; a1.w += v1.w;
    }
    const float4* h0p = (const float4*)(g_h0 + (size_t)node * CH);
    float4 z0 = h0p[lane], z1 = h0p[lane + 32];
    float4 o0, o1;
    o0.x = 0.9f * a0.x + 0.1f * z0.x;  o0.y = 0.9f * a0.y + 0.1f * z0.y;
    o0.z = 0.9f * a0.z + 0.1f * z0.z;  o0.w = 0.9f * a0.w + 0.1f * z0.w;
    o1.x = 0.9f * a1.x + 0.1f * z1.x;  o1.y = 0.9f * a1.y + 0.1f * z1.y;
    o1.z = 0.9f * a1.z + 0.1f * z1.z;  o1.w = 0.9f * a1.w + 0.1f * z1.w;
    float4* xp = (float4*)(g_x + (size_t)node * CH);
    xp[lane] = o0;
    xp[lane + 32] = o1;
}

// ---------------- HMMA GEMM: C = relu(A @ Beff^T (+bias)) -----------------
// A [M,256] fp32, split to bf16 hi/lo in-kernel. B [n][k] bf16 hi/lo (ld=256).
// 3-pass: Ahi*Bhi + Ahi*Blo + Alo*Bhi, fp32 accum in registers.
// CTA: 512 thr (16 warps), tile 128x128, K chunked by 64.
#define KSTR 72   // padded smem k-stride (elements)
#define AS_HI 0
#define AS_LO 18432
#define BS_HI 36864
#define BS_LO 55296
#define SM_TOTAL 73728

__global__ void __launch_bounds__(512, 1)
k_mma_gemm(const float* __restrict__ A,
           const __nv_bfloat16* __restrict__ Bh, const __nv_bfloat16* __restrict__ Bl,
           const float* __restrict__ bias,
           float* __restrict__ C, float* __restrict__ C2, int ccol0, int M) {
    extern __shared__ __align__(16) char smem[];
    const uint32_t sb = smem_u32(smem);
    const int tid = threadIdx.x;
    const int wid = tid >> 5, lane = tid & 31;
    const int wm = wid >> 2, wn = wid & 3;           // 4x4 warp grid
    const int m0 = blockIdx.x * 128;
    const int n0 = blockIdx.y * 128;                 // B row offset

    float acc[2][4][4];
    #pragma unroll
    for (int mt = 0; mt < 2; mt++)
        #pragma unroll
        for (int nt = 0; nt < 4; nt++)
            #pragma unroll
            for (int i = 0; i < 4; i++) acc[mt][nt][i] = 0.f;

    for (int kc = 0; kc < 4; kc++) {
        const int k0 = kc * 64;
        // ---- load + convert A chunk: 128 x 64 fp32 -> hi/lo bf16 ----
        #pragma unroll
        for (int i = 0; i < 4; i++) {
            int idx = tid + i * 512;             // 0..2047 float4 slots
            int m = idx >> 4, kq = (idx & 15) << 2;
            float4 v = make_float4(0.f, 0.f, 0.f, 0.f);
            if (m0 + m < M) v = *(const float4*)(A + (size_t)(m0 + m) * CH + k0 + kq);
            __nv_bfloat16 h0 = __float2bfloat16(v.x);
            __nv_bfloat16 h1 = __float2bfloat16(v.y);
            __nv_bfloat16 h2 = __float2bfloat16(v.z);
            __nv_bfloat16 h3 = __float2bfloat16(v.w);
            __nv_bfloat16 l0 = __float2bfloat16(v.x - __bfloat162float(h0));
            __nv_bfloat16 l1 = __float2bfloat16(v.y - __bfloat162float(h1));
            __nv_bfloat16 l2 = __float2bfloat16(v.z - __bfloat162float(h2));
            __nv_bfloat16 l3 = __float2bfloat16(v.w - __bfloat162float(h3));
            uint32_t hA = (uint32_t)__bfloat16_as_ushort(h0) | ((uint32_t)__bfloat16_as_ushort(h1) << 16);
            uint32_t hB = (uint32_t)__bfloat16_as_ushort(h2) | ((uint32_t)__bfloat16_as_ushort(h3) << 16);
            uint32_t lA = (uint32_t)__bfloat16_as_ushort(l0) | ((uint32_t)__bfloat16_as_ushort(l1) << 16);
            uint32_t lB = (uint32_t)__bfloat16_as_ushort(l2) | ((uint32_t)__bfloat16_as_ushort(l3) << 16);
            int off = (m * KSTR + kq) * 2;
            *(uint2*)(smem + AS_HI + off) = make_uint2(hA, hB);
            *(uint2*)(smem + AS_LO + off) = make_uint2(lA, lB);
        }
        // ---- load B chunk: 128 rows x 64 k of hi and lo ----
        #pragma unroll
        for (int i = 0; i < 2; i++) {
            int idx = tid + i * 512;             // 0..1023 uint4 slots
            int n = idx >> 3, ko8 = (idx & 7) << 3;
            size_t src = (size_t)(n0 + n) * 256 + k0 + ko8;
            int off = (n * KSTR + ko8) * 2;
            *(uint4*)(smem + BS_HI + off) = *(const uint4*)(Bh + src);
            *(uint4*)(smem + BS_LO + off) = *(const uint4*)(Bl + src);
        }
        __syncthreads();

        // ---- compute 4 k16-steps ----
        #pragma unroll
        for (int ks = 0; ks < 4; ks++) {
            const int k = ks * 16;
            uint32_t ah[2][4], al[2][4], bh[4][2], bl[4][2];
            const int arow = wm * 32 + (lane & 15);
            const int akoff = k + (lane >> 4) * 8;
            #pragma unroll
            for (int mt = 0; mt < 2; mt++) {
                int off = ((arow + mt * 16) * KSTR + akoff) * 2;
                ldsm_x4(ah[mt], sb + AS_HI + off);
                ldsm_x4(al[mt], sb + AS_LO + off);
            }
            const int brow = wn * 32 + (lane & 7);
            const int bkoff = k + ((lane >> 3) & 1) * 8;
            #pragma unroll
            for (int nt = 0; nt < 4; nt++) {
                int off = ((brow + nt * 8) * KSTR + bkoff) * 2;
                ldsm_x2(bh[nt], sb + BS_HI + off);
                ldsm_x2(bl[nt], sb + BS_LO + off);
            }
            #pragma unroll
            for (int mt = 0; mt < 2; mt++)
                #pragma unroll
                for (int nt = 0; nt < 4; nt++) {
                    mma16816(acc[mt][nt], ah[mt], bh[nt]);
                    mma16816(acc[mt][nt], ah[mt], bl[nt]);
                    mma16816(acc[mt][nt], al[mt], bh[nt]);
                }
        }
        __syncthreads();
    }

    // ---- epilogue: bias + relu + store ----
    #pragma unroll
    for (int mt = 0; mt < 2; mt++) {
        #pragma unroll
        for (int nt = 0; nt < 4; nt++) {
            int colL = blockIdx.y * 128 + wn * 32 + nt * 8 + (lane & 3) * 2;
            float2 bv = make_float2(0.f, 0.f);
            if (bias) bv = *(const float2*)(bias + colL);
            int colg = ccol0 + colL;
            #pragma unroll
            for (int half = 0; half < 2; half++) {
                int row = m0 + wm * 32 + mt * 16 + (lane >> 2) + half * 8;
                if (row >= M) continue;
                float2 v;
                v.x = fmaxf(acc[mt][nt][half * 2 + 0] + bv.x, 0.f);
                v.y = fmaxf(acc[mt][nt][half * 2 + 1] + bv.y, 0.f);
                *(float2*)(C + (size_t)row * CH + colg) = v;
                if (C2) *(float2*)(C2 + (size_t)row * CH + colg) = v;
            }
        }
    }
}

// ---------------- final projection: out = h @ out_w + out_b  [N,40] ------
__global__ void __launch_bounds__(256)
k_out(const float* __restrict__ H, const float* __restrict__ Wo,
      const float* __restrict__ bo, float* __restrict__ O) {
    __shared__ float As[256][33];
    __shared__ float Ws[32][40];
    const int tid = threadIdx.x;
    const int m0 = blockIdx.x * 256;
    const int rg = tid >> 1;
    const int cg = tid & 1;

    float acc[2][20];
    #pragma unroll
    for (int r = 0; r < 2; r++)
        #pragma unroll
        for (int j = 0; j < 20; j++) acc[r][j] = 0.f;

    for (int kt = 0; kt < CH; kt += 32) {
        #pragma unroll
        for (int i = 0; i < 8; i++) {
            int idx = tid + i * 256;
            int r = idx >> 3, kq = (idx & 7) * 4;
            float4 v = make_float4(0.f, 0.f, 0.f, 0.f);
            int row = m0 + r;
            if (row < NN) v = *(const float4*)(H + (size_t)row * CH + kt + kq);
            As[r][kq + 0] = v.x; As[r][kq + 1] = v.y;
            As[r][kq + 2] = v.z; As[r][kq + 3] = v.w;
        }
        for (int i = tid; i < 32 * NCLS; i += 256)
            Ws[i / NCLS][i % NCLS] = Wo[(size_t)(kt + i / NCLS) * NCLS + (i % NCLS)];
        __syncthreads();
        #pragma unroll
        for (int k = 0; k < 32; k++) {
            float a0 = As[rg * 2 + 0][k];
            float a1 = As[rg * 2 + 1][k];
            #pragma unroll
            for (int j = 0; j < 20; j++) {
                float w = Ws[k][cg * 20 + j];
                acc[0][j] = fmaf(a0, w, acc[0][j]);
                acc[1][j] = fmaf(a1, w, acc[1][j]);
            }
        }
        __syncthreads();
    }
    #pragma unroll
    for (int rr = 0; rr < 2; rr++) {
        int row = m0 + rg * 2 + rr;
        if (row >= NN) continue;
        #pragma unroll
        for (int j = 0; j < 20; j++) {
            int col = cg * 20 + j;
            O[(size_t)row * NCLS + col] = acc[rr][j] + bo[col];
        }
    }
}

// ---------------- launch ----------------
extern "C" void kernel_launch(void* const* d_in, const int* in_sizes, int n_in,
                              void* d_out, int out_size) {
    const float* x0    = (const float*)d_in[0];
    const float* x1    = (const float*)d_in[1];
    const int*   ei    = (const int*)d_in[2];
    const float* lin_w = (const float*)d_in[3];
    const float* lin_b = (const float*)d_in[4];
    const float* gcn_w = (const float*)d_in[5];
    const float* out_w = (const float*)d_in[6];
    const float* out_b = (const float*)d_in[7];
    float* out = (float*)d_out;

    const int* e_src = ei;
    const int* e_dst = ei + EE;

    float *p_h0, *p_h, *p_x;
    __nv_bfloat16 *p_Bh, *p_Bl, *p_BLh, *p_BLl;
    cudaGetSymbolAddress((void**)&p_h0,  g_h0);
    cudaGetSymbolAddress((void**)&p_h,   g_h);
    cudaGetSymbolAddress((void**)&p_x,   g_x);
    cudaGetSymbolAddress((void**)&p_Bh,  g_Bh);
    cudaGetSymbolAddress((void**)&p_Bl,  g_Bl);
    cudaGetSymbolAddress((void**)&p_BLh, g_BLh);
    cudaGetSymbolAddress((void**)&p_BLl, g_BLl);

    cudaFuncSetAttribute(k_mma_gemm, cudaFuncAttributeMaxDynamicSharedMemorySize, SM_TOTAL);

    // weight prep
    k_prep_gcn<<<(LL * 256 * 256 + 255) / 256, 256>>>(gcn_w);
    k_prep_lin<<<(2 * 128 * 256 + 255) / 256, 256>>>(lin_w);

    // CSR build
    k_zero_deg<<<(NN + 255) / 256, 256>>>();
    k_hist<<<(EE + 255) / 256, 256>>>(e_dst);
    k_scan1<<<SCAN_NB, SCAN_BS>>>();
    k_scan2<<<1, 32>>>();
    k_scan3<<<(NN + 255) / 256, 256>>>();
    k_scatter<<<(EE + 255) / 256, 256>>>(e_src, e_dst);

    const int mtiles = (NN + 127) / 128;

    // h0 = concat(relu(x0@W0+b0), relu(x1@W1+b1)); h = h0
    k_mma_gemm<<<dim3(mtiles, 1), 512, SM_TOTAL>>>(x0, p_BLh,         p_BLl,         lin_b,       p_h0, p_h, 0,   NN);
    k_mma_gemm<<<dim3(mtiles, 1), 512, SM_TOTAL>>>(x1, p_BLh + 32768, p_BLl + 32768, lin_b + 128, p_h0, p_h, 128, NN);

    // 8 GCNII layers
    for (int l = 0; l < LL; l++) {
        k_agg<<<(NN + 7) / 8, dim3(32, 8)>>>();
        k_mma_gemm<<<dim3(mtiles, 2), 512, SM_TOTAL>>>(p_x, p_Bh + (size_t)l * 65536,
                                                       p_Bl + (size_t)l * 65536,
                                                       nullptr, p_h, nullptr, 0, NN);
    }

    // output projection
    k_out<<<(NN + 255) / 256, 256>>>(p_h, out_w, out_b, out);
}

// round 4
// speedup vs baseline: 2.0030x; 1.0406x over previous
#include <cuda_runtime.h>
#include <cuda_bf16.h>
#include <math.h>
#include <stdint.h>

#define NN 100000
#define PADN 100096   // 782 * 128
#define EE 300000
#define CH 256
#define LL 8
#define NCLS 40
#define SCAN_BS 1024
#define SCAN_NB 98   // ceil(100000/1024)

// ---------------- helpers ----------------
__device__ __forceinline__ uint32_t smem_u32(const void* p) {
    uint32_t a;
    asm("{ .reg .u64 t; cvta.to.shared.u64 t, %1; cvt.u32.u64 %0, t; }" : "=r"(a) : "l"(p));
    return a;
}
__device__ __forceinline__ void ldsm_x4(uint32_t* r, uint32_t addr) {
    asm volatile("ldmatrix.sync.aligned.m8n8.x4.shared.b16 {%0,%1,%2,%3}, [%4];"
                 : "=r"(r[0]), "=r"(r[1]), "=r"(r[2]), "=r"(r[3]) : "r"(addr));
}
__device__ __forceinline__ void mma16816(float* d, const uint32_t* a, uint32_t b0, uint32_t b1) {
    asm volatile(
        "mma.sync.aligned.m16n8k16.row.col.f32.bf16.bf16.f32 "
        "{%0,%1,%2,%3}, {%4,%5,%6,%7}, {%8,%9}, {%0,%1,%2,%3};"
        : "+f"(d[0]), "+f"(d[1]), "+f"(d[2]), "+f"(d[3])
        : "r"(a[0]), "r"(a[1]), "r"(a[2]), "r"(a[3]), "r"(b0), "r"(b1));
}
#define CP16(dst, src) \
    asm volatile("cp.async.cg.shared.global [%0], [%1], 16;" :: "r"(dst), "l"(src))
#define CP_COMMIT() asm volatile("cp.async.commit_group;" ::: "memory")
#define CP_WAIT(n)  asm volatile("cp.async.wait_group %0;" :: "n"(n) : "memory")

__device__ __forceinline__ uint32_t pack_bf2(float a, float b) {
    return (uint32_t)__bfloat16_as_ushort(__float2bfloat16(a)) |
           ((uint32_t)__bfloat16_as_ushort(__float2bfloat16(b)) << 16);
}

// ---------------- device scratch ----------------
__device__ float g_h0[(size_t)NN * CH];
__device__ float g_h [(size_t)NN * CH];
__device__ __nv_bfloat16 g_xh[(size_t)PADN * CH];   // x hi plane (zero-padded)
__device__ __nv_bfloat16 g_xl[(size_t)PADN * CH];   // x lo plane
__device__ __nv_bfloat16 g_a0h[(size_t)PADN * CH];  // x0 planes
__device__ __nv_bfloat16 g_a0l[(size_t)PADN * CH];
__device__ __nv_bfloat16 g_a1h[(size_t)PADN * CH];  // x1 planes
__device__ __nv_bfloat16 g_a1l[(size_t)PADN * CH];
__device__ __nv_bfloat16 g_Bh [(size_t)LL * 256 * 256];   // gcn eff weights [l][n][k], hi
__device__ __nv_bfloat16 g_Bl [(size_t)LL * 256 * 256];
__device__ __nv_bfloat16 g_BLh[(size_t)2 * 128 * 256];    // lin weights [v][n][k], hi
__device__ __nv_bfloat16 g_BLl[(size_t)2 * 128 * 256];
__device__ int   g_deg[NN];
__device__ int   g_rs [NN];
__device__ int   g_cur[NN];
__device__ int   g_incl[NN];
__device__ int   g_bsum[SCAN_NB];
__device__ int   g_boff[SCAN_NB];
__device__ int   g_csrc[EE];

// ---------------- weight prep ----------------
__global__ void k_prep_gcn(const float* __restrict__ gcn_w) {
    int idx = blockIdx.x * blockDim.x + threadIdx.x;
    if (idx >= LL * 256 * 256) return;
    int l = idx >> 16;
    int n = (idx >> 8) & 255;
    int k = idx & 255;
    float beta = logf(0.5f / (float)(l + 1) + 1.0f);
    float w = gcn_w[l * 65536 + k * 256 + n];
    float eff = beta * w + ((n == k) ? (1.0f - beta) : 0.0f);
    __nv_bfloat16 hi = __float2bfloat16(eff);
    g_Bh[idx] = hi;
    g_Bl[idx] = __float2bfloat16(eff - __bfloat162float(hi));
}
__global__ void k_prep_lin(const float* __restrict__ lin_w) {
    int idx = blockIdx.x * blockDim.x + threadIdx.x;
    if (idx >= 2 * 128 * 256) return;
    int v = idx >> 15;
    int n = (idx >> 8) & 127;
    int k = idx & 255;
    float w = lin_w[v * 32768 + k * 128 + n];
    __nv_bfloat16 hi = __float2bfloat16(w);
    g_BLh[idx] = hi;
    g_BLl[idx] = __float2bfloat16(w - __bfloat162float(hi));
}

// split fp32 input into hi/lo bf16 planes
__global__ void k_split(const float* __restrict__ src,
                        __nv_bfloat16* __restrict__ dh, __nv_bfloat16* __restrict__ dl) {
    int i = blockIdx.x * blockDim.x + threadIdx.x;   // float4 index
    if (i >= NN * 64) return;
    float4 v = *(const float4*)(src + (size_t)i * 4);
    uint32_t h0 = pack_bf2(v.x, v.y), h1 = pack_bf2(v.z, v.w);
    float rx = v.x - __bfloat162float(__float2bfloat16(v.x));
    float ry = v.y - __bfloat162float(__float2bfloat16(v.y));
    float rz = v.z - __bfloat162float(__float2bfloat16(v.z));
    float rw = v.w - __bfloat162float(__float2bfloat16(v.w));
    *(uint2*)(dh + (size_t)i * 4) = make_uint2(h0, h1);
    *(uint2*)(dl + (size_t)i * 4) = make_uint2(pack_bf2(rx, ry), pack_bf2(rz, rw));
}

// ---------------- CSR build ----------------
__global__ void k_zero_deg() {
    int i = blockIdx.x * blockDim.x + threadIdx.x;
    if (i < NN) g_deg[i] = 0;
}
__global__ void k_hist(const int* __restrict__ dst) {
    int e = blockIdx.x * blockDim.x + threadIdx.x;
    if (e < EE) atomicAdd(&g_deg[dst[e]], 1);
}
__global__ void k_scan1() {
    __shared__ int sm[SCAN_BS];
    int tid = threadIdx.x;
    int i = blockIdx.x * SCAN_BS + tid;
    int v = (i < NN) ? g_deg[i] : 0;
    sm[tid] = v;
    __syncthreads();
    for (int off = 1; off < SCAN_BS; off <<= 1) {
        int t = (tid >= off) ? sm[tid - off] : 0;
        __syncthreads();
        sm[tid] += t;
        __syncthreads();
    }
    if (i < NN) g_incl[i] = sm[tid];
    if (tid == SCAN_BS - 1) g_bsum[blockIdx.x] = sm[tid];
}
__global__ void k_scan2() {
    if (threadIdx.x == 0) {
        int s = 0;
        for (int b = 0; b < SCAN_NB; b++) { g_boff[b] = s; s += g_bsum[b]; }
    }
}
__global__ void k_scan3() {
    int i = blockIdx.x * blockDim.x + threadIdx.x;
    if (i >= NN) return;
    int rs = g_boff[i >> 10] + g_incl[i] - g_deg[i];
    g_rs[i] = rs;
    g_cur[i] = rs;
}
__global__ void k_scatter(const int* __restrict__ src, const int* __restrict__ dst) {
    int e = blockIdx.x * blockDim.x + threadIdx.x;
    if (e >= EE) return;
    int p = atomicAdd(&g_cur[dst[e]], 1);
    g_csrc[p] = src[e];
}

// ---- aggregation: x = 0.9*sum h[src] + 0.1*h0, emitted as hi/lo bf16 planes ----
__global__ void k_agg() {
    int node = blockIdx.x * blockDim.y + threadIdx.y;
    if (node >= NN) return;
    int lane = threadIdx.x;
    int s = g_rs[node], d = g_deg[node];
    float4 a0 = make_float4(0.f, 0.f, 0.f, 0.f);
    float4 a1 = make_float4(0.f, 0.f, 0.f, 0.f);
    int e = 0;
    for (; e + 2 <= d; e += 2) {
        int s1 = g_csrc[s + e], s2 = g_csrc[s + e + 1];
        const float4* h1 = (const float4*)(g_h + (size_t)s1 * CH);
        const float4* h2 = (const float4*)(g_h + (size_t)s2 * CH);
        float4 v0 = h1[lane], v1 = h1[lane + 32];
        float4 w0 = h2[lane], w1 = h2[lane + 32];
        a0.x += v0.x + w0.x; a0.y += v0.y + w0.y; a0.z += v0.z + w0.z; a0.w += v0.w + w0.w;
        a1.x += v1.x + w1.x; a1.y += v1.y + w1.y; a1.z += v1.z + w1.z; a1.w += v1.w + w1.w;
    }
    if (e < d) {
        int s1 = g_csrc[s + e];
        const float4* h1 = (const float4*)(g_h + (size_t)s1 * CH);
        float4 v0 = h1[lane], v1 = h1[lane + 32];
        a0.x += v0.x; a0.y += v0.y; a0.z += v0.z; a0.w += v0.w;
        a1.x += v1.x; a1.y += v1.y; a1.z += v1.z; a1.w += v1.w;
    }
    const float4* h0p = (const float4*)(g_h0 + (size_t)node * CH);
    float4 z0 = h0p[lane], z1 = h0p[lane + 32];
    float o[8];
    o[0] = 0.9f * a0.x + 0.1f * z0.x;  o[1] = 0.9f * a0.y + 0.1f * z0.y;
    o[2] = 0.9f * a0.z + 0.1f * z0.z;  o[3] = 0.9f * a0.w + 0.1f * z0.w;
    o[4] = 0.9f * a1.x + 0.1f * z1.x;  o[5] = 0.9f * a1.y + 0.1f * z1.y;
    o[6] = 0.9f * a1.z + 0.1f * z1.z;  o[7] = 0.9f * a1.w + 0.1f * z1.w;
    float r[8];
    #pragma unroll
    for (int i = 0; i < 8; i++) r[i] = o[i] - __bfloat162float(__float2bfloat16(o[i]));
    size_t b0 = (size_t)node * CH + lane * 4;
    size_t b1 = b0 + 128;
    *(uint2*)(g_xh + b0) = make_uint2(pack_bf2(o[0], o[1]), pack_bf2(o[2], o[3]));
    *(uint2*)(g_xh + b1) = make_uint2(pack_bf2(o[4], o[5]), pack_bf2(o[6], o[7]));
    *(uint2*)(g_xl + b0) = make_uint2(pack_bf2(r[0], r[1]), pack_bf2(r[2], r[3]));
    *(uint2*)(g_xl + b1) = make_uint2(pack_bf2(r[4], r[5]), pack_bf2(r[6], r[7]));
}

// ---------------- pipelined HMMA GEMM: C = relu(A @ Beff^T (+bias)) --------
// A: hi/lo bf16 planes [PADN][256]; B: hi/lo [Ndim][256].
// Tile 128 x Ndim (full N), 512 thr (4x4 warps), K in 4 chunks of 64,
// 2-stage cp.async double buffering. 3-pass hi/lo product.
#define KSTRB 144                        // smem row stride bytes (72 bf16)
#define A_PLANE 18432                    // 128*144
template<int NTW>                        // n-tiles(8) per warp: 8 -> N=256, 4 -> N=128
__global__ void __launch_bounds__(512, 1)
k_mma_gemm(const __nv_bfloat16* __restrict__ Ah, const __nv_bfloat16* __restrict__ Al,
           const __nv_bfloat16* __restrict__ Bh, const __nv_bfloat16* __restrict__ Bl,
           const float* __restrict__ bias,
           float* __restrict__ C, float* __restrict__ C2, int ccol0, int M) {
    constexpr int NDIM = NTW * 32;
    constexpr int BN = NDIM * KSTRB;
    constexpr int STAGE = 2 * A_PLANE + 2 * BN;
    extern __shared__ __align__(16) char smem[];
    const uint32_t sb = smem_u32(smem);
    const int tid = threadIdx.x;
    const int wid = tid >> 5, lane = tid & 31;
    const int wm = wid >> 2, wn = wid & 3;
    const int m0 = blockIdx.x * 128;

    float acc[2][NTW][4];
    #pragma unroll
    for (int mt = 0; mt < 2; mt++)
        #pragma unroll
        for (int nt = 0; nt < NTW; nt++)
            #pragma unroll
            for (int i = 0; i < 4; i++) acc[mt][nt][i] = 0.f;

    const int arow_ld = tid >> 3, aseg = tid & 7;   // A: 1024 chunks/plane, 2 iters
    // ---- chunk loader ----
    auto load_chunk = [&](int kc, int st) {
        const int k0 = kc * 64;
        const uint32_t base = sb + st * STAGE;
        #pragma unroll
        for (int i = 0; i < 2; i++) {
            int row = arow_ld + i * 64;
            size_t src = (size_t)(m0 + row) * CH + k0 + aseg * 8;
            uint32_t dst = base + row * KSTRB + aseg * 16;
            CP16(dst, Ah + src);
            CP16(dst + A_PLANE, Al + src);
        }
        #pragma unroll
        for (int i = 0; i < NTW / 2; i++) {
            int idx = tid + i * 512;
            int row = idx >> 3, seg = idx & 7;
            size_t src = (size_t)row * CH + k0 + seg * 8;
            uint32_t dst = base + 2 * A_PLANE + row * KSTRB + seg * 16;
            CP16(dst, Bh + src);
            CP16(dst + BN, Bl + src);
        }
        CP_COMMIT();
    };

    load_chunk(0, 0);

    for (int kc = 0; kc < 4; kc++) {
        if (kc + 1 < 4) load_chunk(kc + 1, (kc + 1) & 1);
        if (kc + 1 < 4) { CP_WAIT(1); } else { CP_WAIT(0); }
        __syncthreads();

        const uint32_t base = sb + (kc & 1) * STAGE;
        const uint32_t sA_hi = base, sA_lo = base + A_PLANE;
        const uint32_t sB_hi = base + 2 * A_PLANE, sB_lo = sB_hi + BN;
        #pragma unroll
        for (int ks = 0; ks < 4; ks++) {
            uint32_t ah[2][4], al[2][4];
            const int arow = wm * 32 + (lane & 15);
            const int akoff = (ks * 16 + (lane >> 4) * 8) * 2;
            #pragma unroll
            for (int mt = 0; mt < 2; mt++) {
                uint32_t off = (uint32_t)(arow + mt * 16) * KSTRB + akoff;
                ldsm_x4(ah[mt], sA_hi + off);
                ldsm_x4(al[mt], sA_lo + off);
            }
            #pragma unroll
            for (int ntp = 0; ntp < NTW / 2; ntp++) {
                const int brow = wn * (NTW * 8) + ntp * 16 + (lane & 15);
                uint32_t off = (uint32_t)brow * KSTRB + akoff;
                uint32_t bh[4], bl[4];
                ldsm_x4(bh, sB_hi + off);
                ldsm_x4(bl, sB_lo + off);
                #pragma unroll
                for (int mt = 0; mt < 2; mt++) {
                    float* a0 = acc[mt][2 * ntp];
                    float* a1 = acc[mt][2 * ntp + 1];
                    mma16816(a0, ah[mt], bh[0], bh[2]);
                    mma16816(a0, ah[mt], bl[0], bl[2]);
                    mma16816(a0, al[mt], bh[0], bh[2]);
                    mma16816(a1, ah[mt], bh[1], bh[3]);
                    mma16816(a1, ah[mt], bl[1], bl[3]);
                    mma16816(a1, al[mt], bh[1], bh[3]);
                }
            }
        }
        __syncthreads();
    }

    // ---- epilogue: bias + relu + store ----
    #pragma unroll
    for (int mt = 0; mt < 2; mt++) {
        #pragma unroll
        for (int nt = 0; nt < NTW; nt++) {
            int colL = wn * (NTW * 8) + nt * 8 + (lane & 3) * 2;
            float2 bv = make_float2(0.f, 0.f);
            if (bias) bv = *(const float2*)(bias + colL);
            int colg = ccol0 + colL;
            #pragma unroll
            for (int half = 0; half < 2; half++) {
                int row = m0 + wm * 32 + mt * 16 + (lane >> 2) + half * 8;
                if (row >= M) continue;
                float2 v;
                v.x = fmaxf(acc[mt][nt][half * 2 + 0] + bv.x, 0.f);
                v.y = fmaxf(acc[mt][nt][half * 2 + 1] + bv.y, 0.f);
                *(float2*)(C + (size_t)row * CH + colg) = v;
                if (C2) *(float2*)(C2 + (size_t)row * CH + colg) = v;
            }
        }
    }
}

// ---------------- final projection: out = h @ out_w + out_b  [N,40] ------
__global__ void __launch_bounds__(256)
k_out(const float* __restrict__ H, const float* __restrict__ Wo,
      const float* __restrict__ bo, float* __restrict__ O) {
    __shared__ float As[256][33];
    __shared__ float Ws[32][40];
    const int tid = threadIdx.x;
    const int m0 = blockIdx.x * 256;
    const int rg = tid >> 1;
    const int cg = tid & 1;

    float acc[2][20];
    #pragma unroll
    for (int r = 0; r < 2; r++)
        #pragma unroll
        for (int j = 0; j < 20; j++) acc[r][j] = 0.f;

    for (int kt = 0; kt < CH; kt += 32) {
        #pragma unroll
        for (int i = 0; i < 8; i++) {
            int idx = tid + i * 256;
            int r = idx >> 3, kq = (idx & 7) * 4;
            float4 v = make_float4(0.f, 0.f, 0.f, 0.f);
            int row = m0 + r;
            if (row < NN) v = *(const float4*)(H + (size_t)row * CH + kt + kq);
            As[r][kq + 0] = v.x; As[r][kq + 1] = v.y;
            As[r][kq + 2] = v.z; As[r][kq + 3] = v.w;
        }
        for (int i = tid; i < 32 * NCLS; i += 256)
            Ws[i / NCLS][i % NCLS] = Wo[(size_t)(kt + i / NCLS) * NCLS + (i % NCLS)];
        __syncthreads();
        #pragma unroll
        for (int k = 0; k < 32; k++) {
            float a0 = As[rg * 2 + 0][k];
            float a1 = As[rg * 2 + 1][k];
            #pragma unroll
            for (int j = 0; j < 20; j++) {
                float w = Ws[k][cg * 20 + j];
                acc[0][j] = fmaf(a0, w, acc[0][j]);
                acc[1][j] = fmaf(a1, w, acc[1][j]);
            }
        }
        __syncthreads();
    }
    #pragma unroll
    for (int rr = 0; rr < 2; rr++) {
        int row = m0 + rg * 2 + rr;
        if (row >= NN) continue;
        #pragma unroll
        for (int j = 0; j < 20; j++) {
            int col = cg * 20 + j;
            O[(size_t)row * NCLS + col] = acc[rr][j] + bo[col];
        }
    }
}

// ---------------- launch ----------------
extern "C" void kernel_launch(void* const* d_in, const int* in_sizes, int n_in,
                              void* d_out, int out_size) {
    const float* x0    = (const float*)d_in[0];
    const float* x1    = (const float*)d_in[1];
    const int*   ei    = (const int*)d_in[2];
    const float* lin_w = (const float*)d_in[3];
    const float* lin_b = (const float*)d_in[4];
    const float* gcn_w = (const float*)d_in[5];
    const float* out_w = (const float*)d_in[6];
    const float* out_b = (const float*)d_in[7];
    float* out = (float*)d_out;

    const int* e_src = ei;
    const int* e_dst = ei + EE;

    float *p_h0, *p_h;
    __nv_bfloat16 *p_xh, *p_xl, *p_a0h, *p_a0l, *p_a1h, *p_a1l;
    __nv_bfloat16 *p_Bh, *p_Bl, *p_BLh, *p_BLl;
    cudaGetSymbolAddress((void**)&p_h0,  g_h0);
    cudaGetSymbolAddress((void**)&p_h,   g_h);
    cudaGetSymbolAddress((void**)&p_xh,  g_xh);
    cudaGetSymbolAddress((void**)&p_xl,  g_xl);
    cudaGetSymbolAddress((void**)&p_a0h, g_a0h);
    cudaGetSymbolAddress((void**)&p_a0l, g_a0l);
    cudaGetSymbolAddress((void**)&p_a1h, g_a1h);
    cudaGetSymbolAddress((void**)&p_a1l, g_a1l);
    cudaGetSymbolAddress((void**)&p_Bh,  g_Bh);
    cudaGetSymbolAddress((void**)&p_Bl,  g_Bl);
    cudaGetSymbolAddress((void**)&p_BLh, g_BLh);
    cudaGetSymbolAddress((void**)&p_BLl, g_BLl);

    const int SM4 = 2 * (2 * A_PLANE + 2 * 128 * KSTRB);   // 147456
    const int SM8 = 2 * (2 * A_PLANE + 2 * 256 * KSTRB);   // 221184
    cudaFuncSetAttribute(k_mma_gemm<4>, cudaFuncAttributeMaxDynamicSharedMemorySize, SM4);
    cudaFuncSetAttribute(k_mma_gemm<8>, cudaFuncAttributeMaxDynamicSharedMemorySize, SM8);

    // weight prep + input split
    k_prep_gcn<<<(LL * 256 * 256 + 255) / 256, 256>>>(gcn_w);
    k_prep_lin<<<(2 * 128 * 256 + 255) / 256, 256>>>(lin_w);
    k_split<<<(NN * 64 + 255) / 256, 256>>>(x0, p_a0h, p_a0l);
    k_split<<<(NN * 64 + 255) / 256, 256>>>(x1, p_a1h, p_a1l);

    // CSR build
    k_zero_deg<<<(NN + 255) / 256, 256>>>();
    k_hist<<<(EE + 255) / 256, 256>>>(e_dst);
    k_scan1<<<SCAN_NB, SCAN_BS>>>();
    k_scan2<<<1, 32>>>();
    k_scan3<<<(NN + 255) / 256, 256>>>();
    k_scatter<<<(EE + 255) / 256, 256>>>(e_src, e_dst);

    const int mtiles = PADN / 128;   // 782

    // h0 = concat(relu(x0@W0+b0), relu(x1@W1+b1)); h = h0
    k_mma_gemm<4><<<mtiles, 512, SM4>>>(p_a0h, p_a0l, p_BLh,         p_BLl,         lin_b,       p_h0, p_h, 0,   NN);
    k_mma_gemm<4><<<mtiles, 512, SM4>>>(p_a1h, p_a1l, p_BLh + 32768, p_BLl + 32768, lin_b + 128, p_h0, p_h, 128, NN);

    // 8 GCNII layers
    for (int l = 0; l < LL; l++) {
        k_agg<<<(NN + 7) / 8, dim3(32, 8)>>>();
        k_mma_gemm<8><<<mtiles, 512, SM8>>>(p_xh, p_xl, p_Bh + (size_t)l * 65536,
                                            p_Bl + (size_t)l * 65536,
                                            nullptr, p_h, nullptr, 0, NN);
    }

    // output projection
    k_out<<<(NN + 255) / 256, 256>>>(p_h, out_w, out_b, out);
}